// round 7
// baseline (speedup 1.0000x reference)
#include <cuda_runtime.h>
#include <float.h>

// SparseSoftmax: masked softmax over last axis of (32, 2048, 2048) fp32
// with int32 mask (mask = OD != 0). Fully-masked rows -> zeros.
//
// Converged configuration (R7 = R5 shape + R1 load policy):
//   - one CTA of 128 threads per row, 16 elements/thread
//   - 4x LDG.128 features + 4x LDG.128 mask front-batched (MLP_p1 = 8)
//   - mask folded to -inf at load time (exp gives exact 0 on masked lanes)
//   - default-policy loads, evict-first (__stcs) stores
// Measured ceiling: ~7.05-7.1 TB/s = GB300 LTS crossbar cap (path-independent);
// traffic is the 1.61 GB minimum, so this sits at the physical floor (~228 us).

#define ROW_LEN 2048
#define THREADS 128
#define EPT     16
#define NWARPS  (THREADS / 32)   // 4

__global__ __launch_bounds__(THREADS)
void sparse_softmax_kernel(const float* __restrict__ f,
                           const int* __restrict__ od,
                           float* __restrict__ out)
{
    const int row = blockIdx.x;
    const size_t base = (size_t)row * ROW_LEN;
    const float4* __restrict__ f4 = reinterpret_cast<const float4*>(f + base);
    const int4*   __restrict__ o4 = reinterpret_cast<const int4*>(od + base);
    float4* __restrict__ out4 = reinterpret_cast<float4*>(out + base);

    const int t    = threadIdx.x;
    const int warp = t >> 5;
    const int lane = t & 31;
    const float NEG_INF = __int_as_float(0xff800000);

    // Front-batched loads: 4x LDG.128 (features) + 4x LDG.128 (mask).
    float4 v0 = f4[t];
    float4 v1 = f4[t + THREADS];
    float4 v2 = f4[t + 2 * THREADS];
    float4 v3 = f4[t + 3 * THREADS];
    int4   m0 = o4[t];
    int4   m1 = o4[t + THREADS];
    int4   m2 = o4[t + 2 * THREADS];
    int4   m3 = o4[t + 3 * THREADS];

    // Fold mask into values: masked-out lanes become -inf (mask regs die here).
    float vals[EPT];
    vals[ 0] = m0.x ? v0.x : NEG_INF;  vals[ 1] = m0.y ? v0.y : NEG_INF;
    vals[ 2] = m0.z ? v0.z : NEG_INF;  vals[ 3] = m0.w ? v0.w : NEG_INF;
    vals[ 4] = m1.x ? v1.x : NEG_INF;  vals[ 5] = m1.y ? v1.y : NEG_INF;
    vals[ 6] = m1.z ? v1.z : NEG_INF;  vals[ 7] = m1.w ? v1.w : NEG_INF;
    vals[ 8] = m2.x ? v2.x : NEG_INF;  vals[ 9] = m2.y ? v2.y : NEG_INF;
    vals[10] = m2.z ? v2.z : NEG_INF;  vals[11] = m2.w ? v2.w : NEG_INF;
    vals[12] = m3.x ? v3.x : NEG_INF;  vals[13] = m3.y ? v3.y : NEG_INF;
    vals[14] = m3.z ? v3.z : NEG_INF;  vals[15] = m3.w ? v3.w : NEG_INF;

    __shared__ float smax[NWARPS];
    __shared__ float ssum[NWARPS];

    // --- max reduce (masked lanes are -inf, harmless) ---
    float mx = NEG_INF;
    #pragma unroll
    for (int i = 0; i < EPT; i++) mx = fmaxf(mx, vals[i]);
    #pragma unroll
    for (int o = 16; o > 0; o >>= 1)
        mx = fmaxf(mx, __shfl_xor_sync(0xffffffffu, mx, o));
    if (lane == 0) smax[warp] = mx;
    __syncthreads();

    float rowmax = smax[0];
    #pragma unroll
    for (int w = 1; w < NWARPS; w++) rowmax = fmaxf(rowmax, smax[w]);
    // Fully-masked row: rowmax = -inf would give NaN in (v - rowmax); clamp.
    if (!(rowmax > NEG_INF)) rowmax = 0.0f;

    // --- exp + sum; exp(-inf - rowmax) = 0 on masked lanes ---
    float sum = 0.0f;
    #pragma unroll
    for (int i = 0; i < EPT; i++) {
        vals[i] = __expf(vals[i] - rowmax);   // overwrite in place: p[i]
        sum += vals[i];
    }
    #pragma unroll
    for (int o = 16; o > 0; o >>= 1)
        sum += __shfl_xor_sync(0xffffffffu, sum, o);
    if (lane == 0) ssum[warp] = sum;
    __syncthreads();

    float s = ssum[0];
    #pragma unroll
    for (int w = 1; w < NWARPS; w++) s += ssum[w];
    const float inv = (s > 0.0f) ? (1.0f / s) : 0.0f;   // fully-masked -> zeros

    // --- normalize + evict-first streaming writes (4x STG.128) ---
    __stcs(&out4[t],
           make_float4(vals[0]*inv, vals[1]*inv, vals[2]*inv, vals[3]*inv));
    __stcs(&out4[t + THREADS],
           make_float4(vals[4]*inv, vals[5]*inv, vals[6]*inv, vals[7]*inv));
    __stcs(&out4[t + 2 * THREADS],
           make_float4(vals[8]*inv, vals[9]*inv, vals[10]*inv, vals[11]*inv));
    __stcs(&out4[t + 3 * THREADS],
           make_float4(vals[12]*inv, vals[13]*inv, vals[14]*inv, vals[15]*inv));
}

extern "C" void kernel_launch(void* const* d_in, const int* in_sizes, int n_in,
                              void* d_out, int out_size)
{
    const float* features = (const float*)d_in[0];
    const int*   OD       = (const int*)d_in[1];
    float*       out      = (float*)d_out;

    const int rows = in_sizes[0] / ROW_LEN;   // 32*2048 = 65536
    sparse_softmax_kernel<<<rows, THREADS>>>(features, OD, out);
}

// round 8
// speedup vs baseline: 1.0018x; 1.0018x over previous
#include <cuda_runtime.h>
#include <float.h>

// SparseSoftmax: masked softmax over last axis of (32, 2048, 2048) fp32
// with int32 mask (mask = OD != 0). Fully-masked rows -> zeros.
//
// FINAL (= R5, best measured 228.7 us):
//   - one CTA of 128 threads per row, 16 elements/thread
//   - 4x LDG.128 features + 4x LDG.128 mask front-batched (MLP_p1 = 8)
//   - mask folded to -inf at load time (exp gives exact 0 on masked lanes)
//   - evict-first streaming loads/stores (pure one-touch stream)
// Converged at the GB300 LTS crossbar cap (~7.05 TB/s path-independent);
// traffic is the 1.61 GB minimum -> ~228 us physical floor, which all
// measured variants (MLP 4/8, occ 72-96%, grid 32k/64k) hit within 0.5%.

#define ROW_LEN 2048
#define THREADS 128
#define EPT     16
#define NWARPS  (THREADS / 32)   // 4

__global__ __launch_bounds__(THREADS)
void sparse_softmax_kernel(const float* __restrict__ f,
                           const int* __restrict__ od,
                           float* __restrict__ out)
{
    const int row = blockIdx.x;
    const size_t base = (size_t)row * ROW_LEN;
    const float4* __restrict__ f4 = reinterpret_cast<const float4*>(f + base);
    const int4*   __restrict__ o4 = reinterpret_cast<const int4*>(od + base);
    float4* __restrict__ out4 = reinterpret_cast<float4*>(out + base);

    const int t    = threadIdx.x;
    const int warp = t >> 5;
    const int lane = t & 31;
    const float NEG_INF = __int_as_float(0xff800000);

    // Front-batched loads: 4x LDG.128 (features) + 4x LDG.128 (mask).
    float4 v0 = __ldcs(&f4[t]);
    float4 v1 = __ldcs(&f4[t + THREADS]);
    float4 v2 = __ldcs(&f4[t + 2 * THREADS]);
    float4 v3 = __ldcs(&f4[t + 3 * THREADS]);
    int4   m0 = __ldcs(&o4[t]);
    int4   m1 = __ldcs(&o4[t + THREADS]);
    int4   m2 = __ldcs(&o4[t + 2 * THREADS]);
    int4   m3 = __ldcs(&o4[t + 3 * THREADS]);

    // Fold mask into values: masked-out lanes become -inf (mask regs die here).
    float vals[EPT];
    vals[ 0] = m0.x ? v0.x : NEG_INF;  vals[ 1] = m0.y ? v0.y : NEG_INF;
    vals[ 2] = m0.z ? v0.z : NEG_INF;  vals[ 3] = m0.w ? v0.w : NEG_INF;
    vals[ 4] = m1.x ? v1.x : NEG_INF;  vals[ 5] = m1.y ? v1.y : NEG_INF;
    vals[ 6] = m1.z ? v1.z : NEG_INF;  vals[ 7] = m1.w ? v1.w : NEG_INF;
    vals[ 8] = m2.x ? v2.x : NEG_INF;  vals[ 9] = m2.y ? v2.y : NEG_INF;
    vals[10] = m2.z ? v2.z : NEG_INF;  vals[11] = m2.w ? v2.w : NEG_INF;
    vals[12] = m3.x ? v3.x : NEG_INF;  vals[13] = m3.y ? v3.y : NEG_INF;
    vals[14] = m3.z ? v3.z : NEG_INF;  vals[15] = m3.w ? v3.w : NEG_INF;

    __shared__ float smax[NWARPS];
    __shared__ float ssum[NWARPS];

    // --- max reduce (masked lanes are -inf, harmless) ---
    float mx = NEG_INF;
    #pragma unroll
    for (int i = 0; i < EPT; i++) mx = fmaxf(mx, vals[i]);
    #pragma unroll
    for (int o = 16; o > 0; o >>= 1)
        mx = fmaxf(mx, __shfl_xor_sync(0xffffffffu, mx, o));
    if (lane == 0) smax[warp] = mx;
    __syncthreads();

    float rowmax = smax[0];
    #pragma unroll
    for (int w = 1; w < NWARPS; w++) rowmax = fmaxf(rowmax, smax[w]);
    // Fully-masked row: rowmax = -inf would give NaN in (v - rowmax); clamp.
    if (!(rowmax > NEG_INF)) rowmax = 0.0f;

    // --- exp + sum; exp(-inf - rowmax) = 0 on masked lanes ---
    float sum = 0.0f;
    #pragma unroll
    for (int i = 0; i < EPT; i++) {
        vals[i] = __expf(vals[i] - rowmax);   // overwrite in place: p[i]
        sum += vals[i];
    }
    #pragma unroll
    for (int o = 16; o > 0; o >>= 1)
        sum += __shfl_xor_sync(0xffffffffu, sum, o);
    if (lane == 0) ssum[warp] = sum;
    __syncthreads();

    float s = ssum[0];
    #pragma unroll
    for (int w = 1; w < NWARPS; w++) s += ssum[w];
    const float inv = (s > 0.0f) ? (1.0f / s) : 0.0f;   // fully-masked -> zeros

    // --- normalize + evict-first streaming writes (4x STG.128) ---
    __stcs(&out4[t],
           make_float4(vals[0]*inv, vals[1]*inv, vals[2]*inv, vals[3]*inv));
    __stcs(&out4[t + THREADS],
           make_float4(vals[4]*inv, vals[5]*inv, vals[6]*inv, vals[7]*inv));
    __stcs(&out4[t + 2 * THREADS],
           make_float4(vals[8]*inv, vals[9]*inv, vals[10]*inv, vals[11]*inv));
    __stcs(&out4[t + 3 * THREADS],
           make_float4(vals[12]*inv, vals[13]*inv, vals[14]*inv, vals[15]*inv));
}

extern "C" void kernel_launch(void* const* d_in, const int* in_sizes, int n_in,
                              void* d_out, int out_size)
{
    const float* features = (const float*)d_in[0];
    const int*   OD       = (const int*)d_in[1];
    float*       out      = (float*)d_out;

    const int rows = in_sizes[0] / ROW_LEN;   // 32*2048 = 65536
    sparse_softmax_kernel<<<rows, THREADS>>>(features, OD, out);
}

// round 9
// speedup vs baseline: 1.0060x; 1.0042x over previous
#include <cuda_runtime.h>
#include <float.h>
#include <stdint.h>

// SparseSoftmax: masked softmax over last axis of (32, 2048, 2048) fp32
// with int32 mask (mask = OD != 0). Fully-masked rows -> zeros.
//
// R9: same converged shape as R5 (128 threads/row, 16 elems/thread), but using
// Blackwell 256-bit vector memory ops: 2x ld.global.nc.v8.f32 (features) +
// 2x ld.global.nc.v8 (mask) + 2x st.global.v8.f32 (output) per thread.
// Halves LSU dispatches and L1tex wavefront entries per byte; byte traffic
// unchanged (pinned at LTS cap ~7.05 TB/s).

#define ROW_LEN 2048
#define THREADS 128
#define EPT     16
#define NWARPS  (THREADS / 32)   // 4

__device__ __forceinline__ void ldg256_f32(float* r, const float* p) {
    asm volatile(
        "ld.global.nc.v8.f32 {%0,%1,%2,%3,%4,%5,%6,%7}, [%8];"
        : "=f"(r[0]), "=f"(r[1]), "=f"(r[2]), "=f"(r[3]),
          "=f"(r[4]), "=f"(r[5]), "=f"(r[6]), "=f"(r[7])
        : "l"(p));
}

__device__ __forceinline__ void ldg256_s32(int* r, const int* p) {
    asm volatile(
        "ld.global.nc.v8.b32 {%0,%1,%2,%3,%4,%5,%6,%7}, [%8];"
        : "=r"(r[0]), "=r"(r[1]), "=r"(r[2]), "=r"(r[3]),
          "=r"(r[4]), "=r"(r[5]), "=r"(r[6]), "=r"(r[7])
        : "l"(p));
}

__device__ __forceinline__ void stg256_f32(float* p, const float* r) {
    asm volatile(
        "st.global.v8.f32 [%0], {%1,%2,%3,%4,%5,%6,%7,%8};"
        :: "l"(p),
           "f"(r[0]), "f"(r[1]), "f"(r[2]), "f"(r[3]),
           "f"(r[4]), "f"(r[5]), "f"(r[6]), "f"(r[7])
        : "memory");
}

__global__ __launch_bounds__(THREADS)
void sparse_softmax_kernel(const float* __restrict__ f,
                           const int* __restrict__ od,
                           float* __restrict__ out)
{
    const int row = blockIdx.x;
    const size_t base = (size_t)row * ROW_LEN;

    const int t    = threadIdx.x;
    const int warp = t >> 5;
    const int lane = t & 31;
    const float NEG_INF = __int_as_float(0xff800000);

    // Two 256-bit feature loads + two 256-bit mask loads per thread.
    // Thread t covers elements [t*8, t*8+8) and [1024 + t*8, 1024 + t*8+8).
    const float* fp0 = f  + base + (size_t)t * 8;
    const float* fp1 = fp0 + ROW_LEN / 2;
    const int*   mp0 = od + base + (size_t)t * 8;
    const int*   mp1 = mp0 + ROW_LEN / 2;

    float vals[EPT];
    int   msk [EPT];
    ldg256_f32(vals,     fp0);
    ldg256_f32(vals + 8, fp1);
    ldg256_s32(msk,      mp0);
    ldg256_s32(msk + 8,  mp1);

    // Fold mask into values: masked-out lanes become -inf.
    #pragma unroll
    for (int i = 0; i < EPT; i++)
        vals[i] = msk[i] ? vals[i] : NEG_INF;

    __shared__ float smax[NWARPS];
    __shared__ float ssum[NWARPS];

    // --- max reduce (masked lanes are -inf, harmless) ---
    float mx = NEG_INF;
    #pragma unroll
    for (int i = 0; i < EPT; i++) mx = fmaxf(mx, vals[i]);
    #pragma unroll
    for (int o = 16; o > 0; o >>= 1)
        mx = fmaxf(mx, __shfl_xor_sync(0xffffffffu, mx, o));
    if (lane == 0) smax[warp] = mx;
    __syncthreads();

    float rowmax = smax[0];
    #pragma unroll
    for (int w = 1; w < NWARPS; w++) rowmax = fmaxf(rowmax, smax[w]);
    // Fully-masked row: rowmax = -inf would give NaN in (v - rowmax); clamp.
    if (!(rowmax > NEG_INF)) rowmax = 0.0f;

    // --- exp + sum; exp(-inf - rowmax) = 0 on masked lanes ---
    float sum = 0.0f;
    #pragma unroll
    for (int i = 0; i < EPT; i++) {
        vals[i] = __expf(vals[i] - rowmax);   // overwrite in place: p[i]
        sum += vals[i];
    }
    #pragma unroll
    for (int o = 16; o > 0; o >>= 1)
        sum += __shfl_xor_sync(0xffffffffu, sum, o);
    if (lane == 0) ssum[warp] = sum;
    __syncthreads();

    float s = ssum[0];
    #pragma unroll
    for (int w = 1; w < NWARPS; w++) s += ssum[w];
    const float inv = (s > 0.0f) ? (1.0f / s) : 0.0f;   // fully-masked -> zeros

    // --- normalize + two 256-bit stores ---
    #pragma unroll
    for (int i = 0; i < EPT; i++) vals[i] *= inv;

    float* op0 = out + base + (size_t)t * 8;
    float* op1 = op0 + ROW_LEN / 2;
    stg256_f32(op0, vals);
    stg256_f32(op1, vals + 8);
}

extern "C" void kernel_launch(void* const* d_in, const int* in_sizes, int n_in,
                              void* d_out, int out_size)
{
    const float* features = (const float*)d_in[0];
    const int*   OD       = (const int*)d_in[1];
    float*       out      = (float*)d_out;

    const int rows = in_sizes[0] / ROW_LEN;   // 32*2048 = 65536
    sparse_softmax_kernel<<<rows, THREADS>>>(features, OD, out);
}